// round 14
// baseline (speedup 1.0000x reference)
#include <cuda_runtime.h>

// DEMA decomposition: x (32, 2048, 512) f32 -> (res, ma) each same shape.
//   s0 = x[:,0,:]; b0 = x[:,1,:] - s0
//   s_t = a*x_t + (1-a)*(s_{t-1} + b_{t-1})
//   b_t = be*(s_t - s_{t-1}) + (1-be)*b_{t-1}
//   ma = [s0..s_{T-1}], res = x - ma
//
// Chunked scan, warmup W=48: state error ~0.837^48 (measured rel_err 2.05e-4).
//
// R13 = R12 two-kernel split (A: entry states from warmup windows, read-only,
// doubles as L2 prefetch of the tail lines; B: zero-warmup pure stream;
// R12 measured B at its traffic floor, 347 MB) + ONE change:
//   float4 -> float2 lanes (256 threads/block). Same bytes/traffic/coalescing,
//   but 2x resident warps (13.8 -> 27.7 per SM). Pump tracks warps across all
//   rounds (13.8 w/SM -> 5.46-5.48 TB/s; 27.7 -> 5.68-5.81), and B is now
//   purely pump-limited. Issue was 9.6% -> headroom for 2x instruction rate.

#define ALPHA 0.3f
#define BETA  0.3f

#define BDIM 32
#define TDIM 2048
#define FDIM 512

#define CHUNK 128
#define WARM  48
#define NCHUNK (TDIM / CHUNK)   // 16
#define F2    (FDIM / 2)        // 256 float2 lanes per row

// Entry states for chunks 1..15: [chunk-1][batch][f2]
__device__ float2 g_state_s[(NCHUNK - 1) * BDIM * F2];
__device__ float2 g_state_u[(NCHUNK - 1) * BDIM * F2];

// (s,u) step, u = s + b:
//   s' = ALPHA*x + (1-ALPHA)*u
//   u' = (1+BETA)*s' + ((1-BETA)*u - s)
__device__ __forceinline__ void dema_step(float2& s, float2& u, const float2 xt) {
    float2 sn, tmp;
    tmp.x = fmaf(1.0f - BETA, u.x, -s.x);
    tmp.y = fmaf(1.0f - BETA, u.y, -s.y);
    sn.x = fmaf(1.0f - ALPHA, u.x, ALPHA * xt.x);
    sn.y = fmaf(1.0f - ALPHA, u.y, ALPHA * xt.y);
    u.x = fmaf(1.0f + BETA, sn.x, tmp.x);
    u.y = fmaf(1.0f + BETA, sn.y, tmp.y);
    s = sn;
}

// Kernel A: entry state for chunk c = blockIdx.x + 1 from its warmup window.
// Plain loads: read-only pass, also inserts the tail lines into L2 for B.
__global__ void __launch_bounds__(F2, 4) dema_states_kernel(
    const float* __restrict__ x)
{
    const int c  = blockIdx.x + 1;   // target chunk 1..15
    const int b  = blockIdx.y;
    const int f2 = threadIdx.x;      // 0..255

    const float2* __restrict__ xb =
        reinterpret_cast<const float2*>(x + (size_t)b * TDIM * FDIM) + f2;

    const int t0 = c * CHUNK;
    const int tw = t0 - WARM;

    float2 s = xb[tw * F2];
    float2 u = xb[(tw + 1) * F2];
    #pragma unroll 8
    for (int tt = tw + 1; tt < t0; ++tt) {
        float2 xt = xb[tt * F2];
        dema_step(s, u, xt);
    }

    const size_t si = ((size_t)(c - 1) * BDIM + b) * F2 + f2;
    g_state_s[si] = s;
    g_state_u[si] = u;
}

// Kernel B: pure streaming pass, no warmup.
__global__ void __launch_bounds__(F2, 4) dema_main_kernel(
    const float* __restrict__ x, float* __restrict__ out)
{
    const int c  = blockIdx.x;       // chunk 0..15
    const int b  = blockIdx.y;
    const int f2 = threadIdx.x;      // 0..255

    const float2* __restrict__ xb =
        reinterpret_cast<const float2*>(x + (size_t)b * TDIM * FDIM) + f2;
    float2* __restrict__ res =
        reinterpret_cast<float2*>(out) + (size_t)b * TDIM * F2 + f2;
    float2* __restrict__ ma =
        reinterpret_cast<float2*>(out + (size_t)BDIM * TDIM * FDIM)
        + (size_t)b * TDIM * F2 + f2;

    const int t0 = c * CHUNK;
    float2 s, u;
    int t;

    if (c == 0) {
        // Exact init: s0 = x0, u0 = x1
        float2 x0 = xb[0];
        float2 x1 = xb[F2];
        s = x0;
        u = x1;
        __stcs(&ma[0], s);
        __stcs(&res[0], make_float2(0.0f, 0.0f));
        t = 1;
    } else {
        const size_t si = ((size_t)(c - 1) * BDIM + b) * F2 + f2;
        s = g_state_s[si];
        u = g_state_u[si];
        t = t0;
    }

    const int tend = t0 + CHUNK;
    #pragma unroll 4
    for (; t < tend; ++t) {
        float2 xt = xb[t * F2];
        dema_step(s, u, xt);
        __stcs(&ma[t * F2], s);
        float2 r;
        r.x = xt.x - s.x; r.y = xt.y - s.y;
        __stcs(&res[t * F2], r);
    }
}

extern "C" void kernel_launch(void* const* d_in, const int* in_sizes, int n_in,
                              void* d_out, int out_size)
{
    const float* x = (const float*)d_in[0];
    float* out = (float*)d_out;
    dim3 gridA(NCHUNK - 1, BDIM);
    dema_states_kernel<<<gridA, F2>>>(x);
    dim3 gridB(NCHUNK, BDIM);
    dema_main_kernel<<<gridB, F2>>>(x, out);
}